// round 2
// baseline (speedup 1.0000x reference)
#include <cuda_runtime.h>

// HMM forward: alpha_t = (alpha_{t-1} @ A) * B[:, obs_t],  out = sum(alpha_{T-1})
// Persistent kernel, A (16 MB) register-resident (128 blocks x 256 thr x 128 regs).
// Inter-step sync: per-block release-flag broadcast + acquire-poll (no atomics,
// no membar on the critical path).

namespace {
constexpr int GRID = 128;
constexpr int NT   = 256;
constexpr int S    = 2048;
constexpr int V    = 32768;
constexpr int T    = 4096;
constexpr int NCOL = S / GRID;  // 16 output columns per block
}

__device__ float    g_alpha[2][S];
__device__ unsigned g_flag[2][GRID];

__device__ __forceinline__ unsigned ld_acq(const unsigned* p) {
    unsigned v;
    asm volatile("ld.global.acquire.gpu.b32 %0, [%1];" : "=r"(v) : "l"(p) : "memory");
    return v;
}
__device__ __forceinline__ void st_rel(unsigned* p, unsigned v) {
    asm volatile("st.global.release.gpu.b32 [%0], %1;" :: "l"(p), "r"(v) : "memory");
}

__global__ void __launch_bounds__(NT, 1) hmm_forward_kernel(
    const int*   __restrict__ obs,
    const float* __restrict__ A,
    const float* __restrict__ B,
    const float* __restrict__ pi,
    float*       __restrict__ out)
{
    __shared__ float4 alpha_s[S / 4];     // 8 KB: current alpha vector
    __shared__ float  red[2][NCOL];       // cross-rowgroup partials
    __shared__ float  bjs[NCOL];          // this step's emission factors

    const int tid  = threadIdx.x;
    const int blk  = blockIdx.x;
    const int w    = tid >> 5;
    const int lane = tid & 31;
    const int cg   = w & 3;               // column group 0..3 (4 cols each)
    const int rg   = w >> 2;              // row group 0..1 (1024 rows each)
    const int jb   = blk * NCOL + cg * 4; // first of this warp's 4 columns
    const int rbase4 = rg * 256;          // float4 base index into alpha_s

    // ---- Load A tile into registers (one time) ----
    float4 areg[8][4];
#pragma unroll
    for (int k = 0; k < 8; k++) {
#pragma unroll
        for (int rr = 0; rr < 4; rr++) {
            int row = rg * 1024 + 4 * lane + 128 * k + rr;
            areg[k][rr] = *reinterpret_cast<const float4*>(&A[(size_t)row * S + jb]);
        }
    }

    // ---- Init: alpha0 = pi * B[:, obs[0]] (step 0, tag 1) ----
    if (tid < NCOL) {
        int   j  = blk * NCOL + tid;
        int   o0 = __ldg(&obs[0]);
        red[0][tid] = pi[j] * __ldg(&B[(size_t)j * V + o0]);
    }
    __syncthreads();
    if (tid == 0) {
        if (blk == 0) *out = 0.0f;   // ordered before the release below
        float4* dst = reinterpret_cast<float4*>(&g_alpha[0][blk * NCOL]);
        const float4* src = reinterpret_cast<const float4*>(red[0]);
#pragma unroll
        for (int q = 0; q < 4; q++) __stcg(&dst[q], src[q]);
        st_rel(&g_flag[0][blk], 1u);
    }
    __syncthreads();

    for (int s = 1; s < T; s++) {
        const int p = (s - 1) & 1;           // buffer holding alpha_{s-1}

        // Prefetch this step's emission factors (independent of alpha).
        if (tid < NCOL) {
            int o = __ldg(&obs[s]);
            bjs[tid] = __ldg(&B[(size_t)(blk * NCOL + tid) * V + o]);
        }

        // Warp 0: acquire-poll all 128 producer tags for step s-1 (tag == s).
        if (tid < 32) {
            const unsigned* f = &g_flag[p][lane * 4];
            const unsigned tag = (unsigned)s;
            for (;;) {
                unsigned v0 = ld_acq(f + 0);
                unsigned v1 = ld_acq(f + 1);
                unsigned v2 = ld_acq(f + 2);
                unsigned v3 = ld_acq(f + 3);
                bool ok = (v0 == tag) & (v1 == tag) & (v2 == tag) & (v3 == tag);
                if (__all_sync(0xffffffffu, ok)) break;
            }
        }
        __syncthreads();

        // Stage alpha (L2 -> SMEM), L1-bypassed.
        const float4* ga = reinterpret_cast<const float4*>(g_alpha[p]);
        alpha_s[tid]       = __ldcg(ga + tid);
        alpha_s[tid + 256] = __ldcg(ga + tid + 256);
        __syncthreads();

        // ---- Matvec slice: 128 FMAs per thread, A from registers ----
        float acc0 = 0.f, acc1 = 0.f, acc2 = 0.f, acc3 = 0.f;
#pragma unroll
        for (int k = 0; k < 8; k++) {
            float4 av = alpha_s[rbase4 + k * 32 + lane];
            float4 a0 = areg[k][0], a1 = areg[k][1], a2 = areg[k][2], a3 = areg[k][3];
            acc0 = fmaf(av.x, a0.x, acc0);
            acc1 = fmaf(av.x, a0.y, acc1);
            acc2 = fmaf(av.x, a0.z, acc2);
            acc3 = fmaf(av.x, a0.w, acc3);
            acc0 = fmaf(av.y, a1.x, acc0);
            acc1 = fmaf(av.y, a1.y, acc1);
            acc2 = fmaf(av.y, a1.z, acc2);
            acc3 = fmaf(av.y, a1.w, acc3);
            acc0 = fmaf(av.z, a2.x, acc0);
            acc1 = fmaf(av.z, a2.y, acc1);
            acc2 = fmaf(av.z, a2.z, acc2);
            acc3 = fmaf(av.z, a2.w, acc3);
            acc0 = fmaf(av.w, a3.x, acc0);
            acc1 = fmaf(av.w, a3.y, acc1);
            acc2 = fmaf(av.w, a3.z, acc2);
            acc3 = fmaf(av.w, a3.w, acc3);
        }

        // Warp reduce (rows split across lanes).
#pragma unroll
        for (int off = 16; off > 0; off >>= 1) {
            acc0 += __shfl_xor_sync(0xffffffffu, acc0, off);
            acc1 += __shfl_xor_sync(0xffffffffu, acc1, off);
            acc2 += __shfl_xor_sync(0xffffffffu, acc2, off);
            acc3 += __shfl_xor_sync(0xffffffffu, acc3, off);
        }
        if (lane == 0) {
            red[rg][cg * 4 + 0] = acc0;
            red[rg][cg * 4 + 1] = acc1;
            red[rg][cg * 4 + 2] = acc2;
            red[rg][cg * 4 + 3] = acc3;
        }
        __syncthreads();

        // Single-thread epilogue: finalize 16 outputs, publish with one release.
        if (tid == 0) {
            const float4* r0 = reinterpret_cast<const float4*>(red[0]);
            const float4* r1 = reinterpret_cast<const float4*>(red[1]);
            const float4* bb = reinterpret_cast<const float4*>(bjs);
            float4 v[4];
#pragma unroll
            for (int q = 0; q < 4; q++) {
                float4 a = r0[q], b = r1[q], c = bb[q];
                v[q].x = (a.x + b.x) * c.x;
                v[q].y = (a.y + b.y) * c.y;
                v[q].z = (a.z + b.z) * c.z;
                v[q].w = (a.w + b.w) * c.w;
            }
            if (s == T - 1) {
                float vs = 0.f;
#pragma unroll
                for (int q = 0; q < 4; q++) vs += v[q].x + v[q].y + v[q].z + v[q].w;
                atomicAdd(out, vs);
            } else {
                float4* dst = reinterpret_cast<float4*>(&g_alpha[s & 1][blk * NCOL]);
#pragma unroll
                for (int q = 0; q < 4; q++) __stcg(&dst[q], v[q]);
                st_rel(&g_flag[s & 1][blk], (unsigned)(s + 1));
            }
        }
        // No block-wide sync needed here: only warp 0 touches the epilogue,
        // and every other warp is gated by the next iteration's first
        // __syncthreads (which warp 0 reaches only after the epilogue).
    }
}

extern "C" void kernel_launch(void* const* d_in, const int* in_sizes, int n_in,
                              void* d_out, int out_size) {
    const int*   obs = (const int*)d_in[0];
    const float* A   = (const float*)d_in[1];
    const float* B   = (const float*)d_in[2];
    const float* pi  = (const float*)d_in[3];
    float*       out = (float*)d_out;
    (void)in_sizes; (void)n_in; (void)out_size;

    hmm_forward_kernel<<<GRID, NT>>>(obs, A, B, pi, out);
}